// round 3
// baseline (speedup 1.0000x reference)
#include <cuda_runtime.h>

// Problem constants
#define BB   4
#define NPTS 16384
#define MPTS 4096
#define CCH  256

// Scratch (device globals; no allocation allowed)
__device__ float g_zT[(size_t)BB * MPTS * CCH];   // [b][m][o]  = (W1[:,C:2C] @ f2[b])^T   16 MB
__device__ float g_y1[(size_t)BB * CCH * NPTS];   // [b][o][n]  first conv output           64 MB
__device__ float g_w [(size_t)BB * NPTS * 4];     // 3 interp weights (+pad)
__device__ int   g_idx[(size_t)BB * NPTS * 4];    // 3 neighbor indices (+pad)

// ---------------------------------------------------------------------------
// Kernel 1: 3-NN. Must reproduce the reference's fp32 arithmetic BIT-EXACTLY
// to avoid neighbor-selection flips near ties (each flip costs ~1e-3 rel_err).
// Reference (XLA, per-op rounding, no FMA contraction):
//   s1 = (x*x + y*y) + z*z          (sequential reduce over 3)
//   s2 = (x*x + y*y) + z*z
//   dot = (x1*x2 + y1*y2) + z1*z2
//   d2  = (s1 + s2) - 2*dot ;  d2 = max(d2, 0)
//   top_k(-d2, 3)  -> stable, lowest index wins ties
//   r_k = 1/(d_k + 1e-8);  w_k = r_k / ((r0+r1)+r2)
// All via __f*_rn intrinsics so neither nvcc contraction nor fast-math can
// alter the rounding.
// ---------------------------------------------------------------------------
__global__ void __launch_bounds__(256) knn_kernel(const float* __restrict__ p1,
                                                  const float* __restrict__ p2)
{
    extern __shared__ float sm[];
    float* sx = sm;
    float* sy = sm + MPTS;
    float* sz = sm + 2 * MPTS;
    float* ss = sm + 3 * MPTS;

    int b = blockIdx.y;
    const float* P2 = p2 + (size_t)b * MPTS * 3;
    for (int i = threadIdx.x; i < MPTS; i += 256) {
        float x = P2[i * 3 + 0];
        float y = P2[i * 3 + 1];
        float z = P2[i * 3 + 2];
        sx[i] = x; sy[i] = y; sz[i] = z;
        ss[i] = __fadd_rn(__fadd_rn(__fmul_rn(x, x), __fmul_rn(y, y)),
                          __fmul_rn(z, z));
    }
    __syncthreads();

    int n = blockIdx.x * 256 + threadIdx.x;
    const float* q = p1 + ((size_t)b * NPTS + n) * 3;
    float px = q[0], py = q[1], pz = q[2];
    float s1 = __fadd_rn(__fadd_rn(__fmul_rn(px, px), __fmul_rn(py, py)),
                         __fmul_rn(pz, pz));

    float d0 = 3.4e38f, d1 = 3.4e38f, d2 = 3.4e38f;
    int   i0 = 0, i1 = 0, i2 = 0;
    for (int m = 0; m < MPTS; ++m) {
        float dot = __fadd_rn(__fadd_rn(__fmul_rn(px, sx[m]),
                                        __fmul_rn(py, sy[m])),
                              __fmul_rn(pz, sz[m]));
        float d = __fadd_rn(s1, ss[m]);
        d = __fsub_rn(d, __fmul_rn(2.0f, dot));
        d = fmaxf(d, 0.0f);
        if (d < d2) {
            if (d < d1) {
                if (d < d0) { d2 = d1; i2 = i1; d1 = d0; i1 = i0; d0 = d; i0 = m; }
                else        { d2 = d1; i2 = i1; d1 = d;  i1 = m; }
            } else          { d2 = d;  i2 = m; }
        }
    }
    float r0 = __fdiv_rn(1.0f, __fadd_rn(d0, 1e-8f));
    float r1 = __fdiv_rn(1.0f, __fadd_rn(d1, 1e-8f));
    float r2 = __fdiv_rn(1.0f, __fadd_rn(d2, 1e-8f));
    float sum = __fadd_rn(__fadd_rn(r0, r1), r2);
    size_t base = ((size_t)b * NPTS + n) * 4;
    g_w[base + 0] = __fdiv_rn(r0, sum);
    g_w[base + 1] = __fdiv_rn(r1, sum);
    g_w[base + 2] = __fdiv_rn(r2, sum);
    g_w[base + 3] = 0.f;
    g_idx[base + 0] = i0;   g_idx[base + 1] = i1;   g_idx[base + 2] = i2;   g_idx[base + 3] = 0;
}

// ---------------------------------------------------------------------------
// SGEMM 128x128x8, 256 threads, 8x8 microtile. All dims divide tiles exactly.
// MODE 0: zGEMM   out = g_zT transposed ([b][m][o]); no bias/relu
// MODE 1: GEMM1   B=f1, epilogue adds 3-NN gather of g_zT + bias + relu -> g_y1
// MODE 2: GEMM2   B=g_y1 (internal), bias + relu -> param out (d_out)
// ---------------------------------------------------------------------------
template <int MODE>
__global__ void __launch_bounds__(256) gemm_k(
    const float* __restrict__ A, int lda,
    const float* __restrict__ B0, long sB, int ldb, int K,
    const float* __restrict__ bias,
    float* __restrict__ O0, long sO, int ldo)
{
    __shared__ float As[8][128];
    __shared__ float Bs[8][128];

    int b  = blockIdx.z;
    int n0 = blockIdx.x * 128;
    int o0 = blockIdx.y * 128;
    int tid = threadIdx.x;
    int tx = tid & 15;       // n direction (8 cols each)
    int ty = tid >> 4;       // o direction (8 rows each)

    const float* Bp = (MODE == 2) ? (g_y1 + (size_t)b * CCH * NPTS)
                                  : (B0 + (size_t)b * sB);

    float acc[8][8];
#pragma unroll
    for (int i = 0; i < 8; ++i)
#pragma unroll
        for (int j = 0; j < 8; ++j) acc[i][j] = 0.0f;

    int arow = tid >> 1;            // 0..127
    int ak   = (tid & 1) * 4;       // 0 or 4
    int bk   = tid >> 5;            // 0..7
    int bc   = (tid & 31) * 4;      // 0..124

    for (int k0 = 0; k0 < K; k0 += 8) {
        float4 av = *(const float4*)&A[(size_t)(o0 + arow) * lda + k0 + ak];
        float4 bv = *(const float4*)&Bp[(size_t)(k0 + bk) * ldb + n0 + bc];
        __syncthreads();
        As[ak + 0][arow] = av.x;
        As[ak + 1][arow] = av.y;
        As[ak + 2][arow] = av.z;
        As[ak + 3][arow] = av.w;
        *(float4*)&Bs[bk][bc] = bv;
        __syncthreads();
#pragma unroll
        for (int kk = 0; kk < 8; ++kk) {
            float4 a0 = *(const float4*)&As[kk][ty * 8];
            float4 a1 = *(const float4*)&As[kk][ty * 8 + 4];
            float4 b0 = *(const float4*)&Bs[kk][tx * 8];
            float4 b1 = *(const float4*)&Bs[kk][tx * 8 + 4];
            float ar[8] = {a0.x, a0.y, a0.z, a0.w, a1.x, a1.y, a1.z, a1.w};
            float br[8] = {b0.x, b0.y, b0.z, b0.w, b1.x, b1.y, b1.z, b1.w};
#pragma unroll
            for (int i = 0; i < 8; ++i)
#pragma unroll
                for (int j = 0; j < 8; ++j)
                    acc[i][j] += ar[i] * br[j];
        }
    }

    if (MODE == 0) {
        // store transposed into g_zT[b][m][o]; o contiguous (coalesced gather later)
#pragma unroll
        for (int j = 0; j < 8; ++j) {
            int m = n0 + tx * 8 + j;
            size_t base = ((size_t)b * MPTS + m) * CCH + o0 + ty * 8;
            float4 v0 = make_float4(acc[0][j], acc[1][j], acc[2][j], acc[3][j]);
            float4 v1 = make_float4(acc[4][j], acc[5][j], acc[6][j], acc[7][j]);
            *(float4*)&g_zT[base]     = v0;
            *(float4*)&g_zT[base + 4] = v1;
        }
        return;
    }

    if (MODE == 1) {
        // gather epilogue: acc[:,j] += sum_k w_k * zT[b][idx_k][o...]
#pragma unroll
        for (int j = 0; j < 8; ++j) {
            int n = n0 + tx * 8 + j;
            size_t wb = ((size_t)b * NPTS + n) * 4;
            float4 w4 = *(const float4*)&g_w[wb];
            int4   i4 = *(const int4*)&g_idx[wb];
            float wk[3] = {w4.x, w4.y, w4.z};
            int   ik[3] = {i4.x, i4.y, i4.z};
#pragma unroll
            for (int t = 0; t < 3; ++t) {
                const float* zp = &g_zT[((size_t)b * MPTS + ik[t]) * CCH + o0 + ty * 8];
                float4 z0 = *(const float4*)zp;
                float4 z1 = *(const float4*)(zp + 4);
                acc[0][j] += wk[t] * z0.x;
                acc[1][j] += wk[t] * z0.y;
                acc[2][j] += wk[t] * z0.z;
                acc[3][j] += wk[t] * z0.w;
                acc[4][j] += wk[t] * z1.x;
                acc[5][j] += wk[t] * z1.y;
                acc[6][j] += wk[t] * z1.z;
                acc[7][j] += wk[t] * z1.w;
            }
        }
    }

    float* Op = (MODE == 1) ? (g_y1 + (size_t)b * CCH * NPTS)
                            : (O0 + (size_t)b * sO);
    int ldn = (MODE == 1) ? NPTS : ldo;
#pragma unroll
    for (int i = 0; i < 8; ++i) {
        int o = o0 + ty * 8 + i;
        float bv = bias[o];
        float4 v0, v1;
        v0.x = fmaxf(acc[i][0] + bv, 0.0f);
        v0.y = fmaxf(acc[i][1] + bv, 0.0f);
        v0.z = fmaxf(acc[i][2] + bv, 0.0f);
        v0.w = fmaxf(acc[i][3] + bv, 0.0f);
        v1.x = fmaxf(acc[i][4] + bv, 0.0f);
        v1.y = fmaxf(acc[i][5] + bv, 0.0f);
        v1.z = fmaxf(acc[i][6] + bv, 0.0f);
        v1.w = fmaxf(acc[i][7] + bv, 0.0f);
        size_t base = (size_t)o * ldn + n0 + tx * 8;
        *(float4*)&Op[base]     = v0;
        *(float4*)&Op[base + 4] = v1;
    }
}

// ---------------------------------------------------------------------------
extern "C" void kernel_launch(void* const* d_in, const int* in_sizes, int n_in,
                              void* d_out, int out_size)
{
    const float* p1 = (const float*)d_in[0];
    const float* f1 = (const float*)d_in[1];
    const float* p2 = (const float*)d_in[2];
    const float* f2 = (const float*)d_in[3];
    const float* W1 = (const float*)d_in[4];
    const float* b1 = (const float*)d_in[5];
    const float* W2 = (const float*)d_in[6];
    const float* b2 = (const float*)d_in[7];
    float* out = (float*)d_out;

    // 1) 3-NN weights/indices (64KB dynamic smem: x,y,z,|p2|^2)
    static int smem_set = 0;
    if (!smem_set) {
        cudaFuncSetAttribute(knn_kernel, cudaFuncAttributeMaxDynamicSharedMemorySize,
                             4 * MPTS * (int)sizeof(float));
        smem_set = 1;
    }
    knn_kernel<<<dim3(NPTS / 256, BB), 256, 4 * MPTS * sizeof(float)>>>(p1, p2);

    // 2) zT[b][m][o] = (W1[:, C:2C] @ f2[b])^T    (A row stride = 2C)
    gemm_k<0><<<dim3(MPTS / 128, CCH / 128, BB), 256>>>(
        W1 + CCH, 2 * CCH, f2, (long)CCH * MPTS, MPTS, CCH,
        nullptr, nullptr, 0, 0);

    // 3) y1 = relu(W1[:, 0:C] @ f1 + gather(zT) + b1)
    gemm_k<1><<<dim3(NPTS / 128, CCH / 128, BB), 256>>>(
        W1, 2 * CCH, f1, (long)CCH * NPTS, NPTS, CCH,
        b1, nullptr, 0, 0);

    // 4) out = relu(W2 @ y1 + b2)
    gemm_k<2><<<dim3(NPTS / 128, CCH / 128, BB), 256>>>(
        W2, CCH, nullptr, 0, NPTS, CCH,
        b2, out, (long)CCH * NPTS, NPTS);
}

// round 4
// speedup vs baseline: 1.2087x; 1.2087x over previous
#include <cuda_runtime.h>

// Problem constants
#define BB   4
#define NPTS 16384
#define MPTS 4096
#define CCH  256

// Scratch (device globals; no allocation allowed)
__device__ float g_zT[(size_t)BB * MPTS * CCH];   // [b][m][o]  = (W1[:,C:2C] @ f2[b])^T   16 MB
__device__ float g_y1[(size_t)BB * CCH * NPTS];   // [b][o][n]  first conv output           64 MB
__device__ float g_w [(size_t)BB * NPTS * 4];     // 3 interp weights (+pad)
__device__ int   g_idx[(size_t)BB * NPTS * 4];    // 3 neighbor indices (+pad)

__device__ __forceinline__ void cp_async16(void* smem_dst, const void* gmem_src) {
    unsigned s = (unsigned)__cvta_generic_to_shared(smem_dst);
    asm volatile("cp.async.cg.shared.global [%0], [%1], 16;\n" :: "r"(s), "l"(gmem_src));
}
#define CP_COMMIT() asm volatile("cp.async.commit_group;\n" ::: "memory")
#define CP_WAIT0()  asm volatile("cp.async.wait_group 0;\n" ::: "memory")

// ---------------------------------------------------------------------------
// Kernel 1: 3-NN. Reproduces the reference's fp32 arithmetic BIT-EXACTLY
// (per-op rounding, no FMA contraction) to avoid neighbor-selection flips.
// ---------------------------------------------------------------------------
__global__ void __launch_bounds__(256) knn_kernel(const float* __restrict__ p1,
                                                  const float* __restrict__ p2)
{
    extern __shared__ float sm[];
    float* sx = sm;
    float* sy = sm + MPTS;
    float* sz = sm + 2 * MPTS;
    float* ss = sm + 3 * MPTS;

    int b = blockIdx.y;
    const float* P2 = p2 + (size_t)b * MPTS * 3;
    for (int i = threadIdx.x; i < MPTS; i += 256) {
        float x = P2[i * 3 + 0];
        float y = P2[i * 3 + 1];
        float z = P2[i * 3 + 2];
        sx[i] = x; sy[i] = y; sz[i] = z;
        ss[i] = __fadd_rn(__fadd_rn(__fmul_rn(x, x), __fmul_rn(y, y)),
                          __fmul_rn(z, z));
    }
    __syncthreads();

    int n = blockIdx.x * 256 + threadIdx.x;
    const float* q = p1 + ((size_t)b * NPTS + n) * 3;
    float px = q[0], py = q[1], pz = q[2];
    float s1 = __fadd_rn(__fadd_rn(__fmul_rn(px, px), __fmul_rn(py, py)),
                         __fmul_rn(pz, pz));

    float d0 = 3.4e38f, d1 = 3.4e38f, d2 = 3.4e38f;
    int   i0 = 0, i1 = 0, i2 = 0;
    for (int m = 0; m < MPTS; ++m) {
        float dot = __fadd_rn(__fadd_rn(__fmul_rn(px, sx[m]),
                                        __fmul_rn(py, sy[m])),
                              __fmul_rn(pz, sz[m]));
        float d = __fadd_rn(s1, ss[m]);
        d = __fsub_rn(d, __fmul_rn(2.0f, dot));
        d = fmaxf(d, 0.0f);
        if (d < d2) {
            if (d < d1) {
                if (d < d0) { d2 = d1; i2 = i1; d1 = d0; i1 = i0; d0 = d; i0 = m; }
                else        { d2 = d1; i2 = i1; d1 = d;  i1 = m; }
            } else          { d2 = d;  i2 = m; }
        }
    }
    float r0 = __fdiv_rn(1.0f, __fadd_rn(d0, 1e-8f));
    float r1 = __fdiv_rn(1.0f, __fadd_rn(d1, 1e-8f));
    float r2 = __fdiv_rn(1.0f, __fadd_rn(d2, 1e-8f));
    float sum = __fadd_rn(__fadd_rn(r0, r1), r2);
    size_t base = ((size_t)b * NPTS + n) * 4;
    g_w[base + 0] = __fdiv_rn(r0, sum);
    g_w[base + 1] = __fdiv_rn(r1, sum);
    g_w[base + 2] = __fdiv_rn(r2, sum);
    g_w[base + 3] = 0.f;
    g_idx[base + 0] = i0;   g_idx[base + 1] = i1;   g_idx[base + 2] = i2;   g_idx[base + 3] = 0;
}

// ---------------------------------------------------------------------------
// SGEMM 128x128, kTile=16, double-buffered (cp.async for B, reg-prefetch A),
// 256 threads, 8x8 microtile, 1 barrier per k-step.
// MODE 0: zGEMM   out = g_zT transposed ([b][m][o]); no bias/relu
// MODE 1: GEMM1   B=f1, epilogue adds 3-NN gather of g_zT + bias + relu -> g_y1
// MODE 2: GEMM2   B=g_y1 (internal), bias + relu -> param out (d_out)
// Accumulation order identical to the verified R3 kernel.
// ---------------------------------------------------------------------------
template <int MODE>
__global__ void __launch_bounds__(256, 2) gemm_k(
    const float* __restrict__ A, int lda,
    const float* __restrict__ B0, long sB, int ldb, int K,
    const float* __restrict__ bias,
    float* __restrict__ O0, long sO, int ldo)
{
    __shared__ float As[2][16][132];   // padded stride: conflict-free transposed store
    __shared__ float Bs[2][16][128];

    int b  = blockIdx.z;
    int n0 = blockIdx.x * 128;
    int o0 = blockIdx.y * 128;
    int tid = threadIdx.x;
    int tx = tid & 15;       // n direction (8 cols each)
    int ty = tid >> 4;       // o direction (8 rows each)

    const float* Bp = (MODE == 2) ? (g_y1 + (size_t)b * CCH * NPTS)
                                  : (B0 + (size_t)b * sB);

    // A mapping: thread handles rows (tid>>2) and (tid>>2)+64, k-part (tid&3)*4
    int ar  = tid >> 2;
    int ak  = (tid & 3) * 4;
    const float* Ap0 = A + (size_t)(o0 + ar) * lda + ak;
    const float* Ap1 = A + (size_t)(o0 + ar + 64) * lda + ak;
    // B mapping: cp.async rows (tid>>5) and (tid>>5)+8, col (tid&31)*4
    int br  = tid >> 5;
    int bc  = (tid & 31) * 4;
    const float* Bp0 = Bp + (size_t)br * ldb + n0 + bc;
    const float* Bp1 = Bp + (size_t)(br + 8) * ldb + n0 + bc;

    float acc[8][8];
#pragma unroll
    for (int i = 0; i < 8; ++i)
#pragma unroll
        for (int j = 0; j < 8; ++j) acc[i][j] = 0.0f;

    // ---- prologue: stage 0 ----
    {
        float4 a0 = *(const float4*)Ap0;
        float4 a1 = *(const float4*)Ap1;
        As[0][ak + 0][ar]      = a0.x;
        As[0][ak + 1][ar]      = a0.y;
        As[0][ak + 2][ar]      = a0.z;
        As[0][ak + 3][ar]      = a0.w;
        As[0][ak + 0][ar + 64] = a1.x;
        As[0][ak + 1][ar + 64] = a1.y;
        As[0][ak + 2][ar + 64] = a1.z;
        As[0][ak + 3][ar + 64] = a1.w;
        cp_async16(&Bs[0][br][bc],     Bp0);
        cp_async16(&Bs[0][br + 8][bc], Bp1);
        CP_COMMIT();
    }
    CP_WAIT0();
    __syncthreads();

    int cur = 0;
    for (int k0 = 0; k0 < K; k0 += 16) {
        bool nxt = (k0 + 16) < K;
        float4 a0, a1;
        if (nxt) {
            a0 = *(const float4*)(Ap0 + k0 + 16);
            a1 = *(const float4*)(Ap1 + k0 + 16);
            cp_async16(&Bs[cur ^ 1][br][bc],     Bp0 + (size_t)(k0 + 16) * ldb);
            cp_async16(&Bs[cur ^ 1][br + 8][bc], Bp1 + (size_t)(k0 + 16) * ldb);
            CP_COMMIT();
        }
#pragma unroll
        for (int kk = 0; kk < 16; ++kk) {
            float4 x0 = *(const float4*)&As[cur][kk][ty * 8];
            float4 x1 = *(const float4*)&As[cur][kk][ty * 8 + 4];
            float4 y0 = *(const float4*)&Bs[cur][kk][tx * 8];
            float4 y1 = *(const float4*)&Bs[cur][kk][tx * 8 + 4];
            float ar8[8] = {x0.x, x0.y, x0.z, x0.w, x1.x, x1.y, x1.z, x1.w};
            float br8[8] = {y0.x, y0.y, y0.z, y0.w, y1.x, y1.y, y1.z, y1.w};
#pragma unroll
            for (int i = 0; i < 8; ++i)
#pragma unroll
                for (int j = 0; j < 8; ++j)
                    acc[i][j] += ar8[i] * br8[j];
        }
        if (nxt) {
            int nb = cur ^ 1;
            As[nb][ak + 0][ar]      = a0.x;
            As[nb][ak + 1][ar]      = a0.y;
            As[nb][ak + 2][ar]      = a0.z;
            As[nb][ak + 3][ar]      = a0.w;
            As[nb][ak + 0][ar + 64] = a1.x;
            As[nb][ak + 1][ar + 64] = a1.y;
            As[nb][ak + 2][ar + 64] = a1.z;
            As[nb][ak + 3][ar + 64] = a1.w;
        }
        CP_WAIT0();
        __syncthreads();
        cur ^= 1;
    }

    if (MODE == 0) {
        // store transposed into g_zT[b][m][o]; o contiguous (coalesced gather later)
#pragma unroll
        for (int j = 0; j < 8; ++j) {
            int m = n0 + tx * 8 + j;
            size_t base = ((size_t)b * MPTS + m) * CCH + o0 + ty * 8;
            float4 v0 = make_float4(acc[0][j], acc[1][j], acc[2][j], acc[3][j]);
            float4 v1 = make_float4(acc[4][j], acc[5][j], acc[6][j], acc[7][j]);
            *(float4*)&g_zT[base]     = v0;
            *(float4*)&g_zT[base + 4] = v1;
        }
        return;
    }

    if (MODE == 1) {
        // gather epilogue: acc[:,j] += sum_k w_k * zT[b][idx_k][o...]
#pragma unroll
        for (int j = 0; j < 8; ++j) {
            int n = n0 + tx * 8 + j;
            size_t wb = ((size_t)b * NPTS + n) * 4;
            float4 w4 = *(const float4*)&g_w[wb];
            int4   i4 = *(const int4*)&g_idx[wb];
            float wk[3] = {w4.x, w4.y, w4.z};
            int   ik[3] = {i4.x, i4.y, i4.z};
#pragma unroll
            for (int t = 0; t < 3; ++t) {
                const float* zp = &g_zT[((size_t)b * MPTS + ik[t]) * CCH + o0 + ty * 8];
                float4 z0 = *(const float4*)zp;
                float4 z1 = *(const float4*)(zp + 4);
                acc[0][j] += wk[t] * z0.x;
                acc[1][j] += wk[t] * z0.y;
                acc[2][j] += wk[t] * z0.z;
                acc[3][j] += wk[t] * z0.w;
                acc[4][j] += wk[t] * z1.x;
                acc[5][j] += wk[t] * z1.y;
                acc[6][j] += wk[t] * z1.z;
                acc[7][j] += wk[t] * z1.w;
            }
        }
    }

    float* Op = (MODE == 1) ? (g_y1 + (size_t)b * CCH * NPTS)
                            : (O0 + (size_t)b * sO);
    int ldn = (MODE == 1) ? NPTS : ldo;
#pragma unroll
    for (int i = 0; i < 8; ++i) {
        int o = o0 + ty * 8 + i;
        float bv = bias[o];
        float4 v0, v1;
        v0.x = fmaxf(acc[i][0] + bv, 0.0f);
        v0.y = fmaxf(acc[i][1] + bv, 0.0f);
        v0.z = fmaxf(acc[i][2] + bv, 0.0f);
        v0.w = fmaxf(acc[i][3] + bv, 0.0f);
        v1.x = fmaxf(acc[i][4] + bv, 0.0f);
        v1.y = fmaxf(acc[i][5] + bv, 0.0f);
        v1.z = fmaxf(acc[i][6] + bv, 0.0f);
        v1.w = fmaxf(acc[i][7] + bv, 0.0f);
        size_t base = (size_t)o * ldn + n0 + tx * 8;
        *(float4*)&Op[base]     = v0;
        *(float4*)&Op[base + 4] = v1;
    }
}

// ---------------------------------------------------------------------------
extern "C" void kernel_launch(void* const* d_in, const int* in_sizes, int n_in,
                              void* d_out, int out_size)
{
    const float* p1 = (const float*)d_in[0];
    const float* f1 = (const float*)d_in[1];
    const float* p2 = (const float*)d_in[2];
    const float* f2 = (const float*)d_in[3];
    const float* W1 = (const float*)d_in[4];
    const float* b1 = (const float*)d_in[5];
    const float* W2 = (const float*)d_in[6];
    const float* b2 = (const float*)d_in[7];
    float* out = (float*)d_out;

    // 1) 3-NN weights/indices (64KB dynamic smem: x,y,z,|p2|^2)
    cudaFuncSetAttribute(knn_kernel, cudaFuncAttributeMaxDynamicSharedMemorySize,
                         4 * MPTS * (int)sizeof(float));
    knn_kernel<<<dim3(NPTS / 256, BB), 256, 4 * MPTS * sizeof(float)>>>(p1, p2);

    // 2) zT[b][m][o] = (W1[:, C:2C] @ f2[b])^T    (A row stride = 2C)
    gemm_k<0><<<dim3(MPTS / 128, CCH / 128, BB), 256>>>(
        W1 + CCH, 2 * CCH, f2, (long)CCH * MPTS, MPTS, CCH,
        nullptr, nullptr, 0, 0);

    // 3) y1 = relu(W1[:, 0:C] @ f1 + gather(zT) + b1)
    gemm_k<1><<<dim3(NPTS / 128, CCH / 128, BB), 256>>>(
        W1, 2 * CCH, f1, (long)CCH * NPTS, NPTS, CCH,
        b1, nullptr, 0, 0);

    // 4) out = relu(W2 @ y1 + b2)
    gemm_k<2><<<dim3(NPTS / 128, CCH / 128, BB), 256>>>(
        W2, CCH, nullptr, 0, NPTS, CCH,
        b2, out, (long)CCH * NPTS, NPTS);
}

// round 5
// speedup vs baseline: 1.3588x; 1.1242x over previous
#include <cuda_runtime.h>

// Problem constants
#define BB   4
#define NPTS 16384
#define MPTS 4096
#define CCH  256

// Scratch (device globals; no allocation allowed)
__device__ float g_zT[(size_t)BB * MPTS * CCH];   // [b][m][o]
__device__ float g_y1[(size_t)BB * CCH * NPTS];   // [b][o][n]
__device__ float g_w [(size_t)BB * NPTS * 4];
__device__ int   g_idx[(size_t)BB * NPTS * 4];

__device__ __forceinline__ void cp_async16(void* smem_dst, const void* gmem_src) {
    unsigned s = (unsigned)__cvta_generic_to_shared(smem_dst);
    asm volatile("cp.async.cg.shared.global [%0], [%1], 16;\n" :: "r"(s), "l"(gmem_src));
}
#define CP_COMMIT() asm volatile("cp.async.commit_group;\n" ::: "memory")
#define CP_WAIT0()  asm volatile("cp.async.wait_group 0;\n" ::: "memory")

extern __shared__ float sm_f[];

// ---------------------------------------------------------------------------
// kNN body: bit-exact reproduction of the reference's per-op fp32 rounding.
// smem holds packed float4 {x, y, z, |p|^2} per coarse point (64KB).
// ---------------------------------------------------------------------------
__device__ __forceinline__ void knn_body(const float* __restrict__ p1,
                                         const float* __restrict__ p2,
                                         int tile, int b)
{
    float4* sp = (float4*)sm_f;
    const float* P2 = p2 + (size_t)b * MPTS * 3;
    for (int i = threadIdx.x; i < MPTS; i += 256) {
        float x = P2[i * 3 + 0];
        float y = P2[i * 3 + 1];
        float z = P2[i * 3 + 2];
        float s = __fadd_rn(__fadd_rn(__fmul_rn(x, x), __fmul_rn(y, y)),
                            __fmul_rn(z, z));
        sp[i] = make_float4(x, y, z, s);
    }
    __syncthreads();

    int n = tile * 256 + threadIdx.x;
    const float* q = p1 + ((size_t)b * NPTS + n) * 3;
    float px = q[0], py = q[1], pz = q[2];
    float s1 = __fadd_rn(__fadd_rn(__fmul_rn(px, px), __fmul_rn(py, py)),
                         __fmul_rn(pz, pz));

    float d0 = 3.4e38f, d1 = 3.4e38f, d2 = 3.4e38f;
    int   i0 = 0, i1 = 0, i2 = 0;
    for (int m = 0; m < MPTS; ++m) {
        float4 c = sp[m];
        float dot = __fadd_rn(__fadd_rn(__fmul_rn(px, c.x),
                                        __fmul_rn(py, c.y)),
                              __fmul_rn(pz, c.z));
        float d = __fadd_rn(s1, c.w);
        d = __fsub_rn(d, __fmul_rn(2.0f, dot));
        d = fmaxf(d, 0.0f);
        if (d < d2) {
            if (d < d1) {
                if (d < d0) { d2 = d1; i2 = i1; d1 = d0; i1 = i0; d0 = d; i0 = m; }
                else        { d2 = d1; i2 = i1; d1 = d;  i1 = m; }
            } else          { d2 = d;  i2 = m; }
        }
    }
    float r0 = __fdiv_rn(1.0f, __fadd_rn(d0, 1e-8f));
    float r1 = __fdiv_rn(1.0f, __fadd_rn(d1, 1e-8f));
    float r2 = __fdiv_rn(1.0f, __fadd_rn(d2, 1e-8f));
    float sum = __fadd_rn(__fadd_rn(r0, r1), r2);
    size_t base = ((size_t)b * NPTS + n) * 4;
    g_w[base + 0] = __fdiv_rn(r0, sum);
    g_w[base + 1] = __fdiv_rn(r1, sum);
    g_w[base + 2] = __fdiv_rn(r2, sum);
    g_w[base + 3] = 0.f;
    g_idx[base + 0] = i0; g_idx[base + 1] = i1; g_idx[base + 2] = i2; g_idx[base + 3] = 0;
}

// ---------------------------------------------------------------------------
// SGEMM 128x128 tile, kTile=16, double-buffered (cp.async B, reg-prefetch A).
// Conflict-free 4+4 split microtile: thread owns A rows {ty*4..+3, +64} and
// B cols {tx*4..+3, +64}. Fragment LDS are lane-consecutive (no conflicts).
// Per-element accumulation order identical to previous passing kernel.
// ---------------------------------------------------------------------------
template <int MODE>
__device__ __forceinline__ void gemm_body(
    const float* __restrict__ A, int lda,
    const float* __restrict__ Bp, int ldb, int K,
    const float* __restrict__ bias,
    float* __restrict__ Op, int ldn,
    int n0, int o0, int b)
{
    float (*As)[16][132] = (float(*)[16][132])sm_f;               // 2*16*132*4 = 16896B
    float (*Bs)[16][128] = (float(*)[16][128])(sm_f + 2*16*132);  // 2*16*128*4 = 16384B

    int tid = threadIdx.x;
    int tx = tid & 15;
    int ty = tid >> 4;

    int ar = tid >> 2;
    int ak = (tid & 3) * 4;
    const float* Ap0 = A + (size_t)(o0 + ar) * lda + ak;
    const float* Ap1 = A + (size_t)(o0 + ar + 64) * lda + ak;
    int brr = tid >> 5;
    int bc  = (tid & 31) * 4;
    const float* Bp0 = Bp + (size_t)brr * ldb + n0 + bc;
    const float* Bp1 = Bp + (size_t)(brr + 8) * ldb + n0 + bc;

    float acc[8][8];
#pragma unroll
    for (int i = 0; i < 8; ++i)
#pragma unroll
        for (int j = 0; j < 8; ++j) acc[i][j] = 0.0f;

    // prologue: stage 0
    {
        float4 a0 = *(const float4*)Ap0;
        float4 a1 = *(const float4*)Ap1;
        As[0][ak + 0][ar]      = a0.x;
        As[0][ak + 1][ar]      = a0.y;
        As[0][ak + 2][ar]      = a0.z;
        As[0][ak + 3][ar]      = a0.w;
        As[0][ak + 0][ar + 64] = a1.x;
        As[0][ak + 1][ar + 64] = a1.y;
        As[0][ak + 2][ar + 64] = a1.z;
        As[0][ak + 3][ar + 64] = a1.w;
        cp_async16(&Bs[0][brr][bc],     Bp0);
        cp_async16(&Bs[0][brr + 8][bc], Bp1);
        CP_COMMIT();
    }
    CP_WAIT0();
    __syncthreads();

    int cur = 0;
    for (int k0 = 0; k0 < K; k0 += 16) {
        bool nxt = (k0 + 16) < K;
        float4 a0, a1;
        if (nxt) {
            a0 = *(const float4*)(Ap0 + k0 + 16);
            a1 = *(const float4*)(Ap1 + k0 + 16);
            cp_async16(&Bs[cur ^ 1][brr][bc],     Bp0 + (size_t)(k0 + 16) * ldb);
            cp_async16(&Bs[cur ^ 1][brr + 8][bc], Bp1 + (size_t)(k0 + 16) * ldb);
            CP_COMMIT();
        }
#pragma unroll
        for (int kk = 0; kk < 16; ++kk) {
            float4 x0 = *(const float4*)&As[cur][kk][ty * 4];
            float4 x1 = *(const float4*)&As[cur][kk][ty * 4 + 64];
            float4 y0 = *(const float4*)&Bs[cur][kk][tx * 4];
            float4 y1 = *(const float4*)&Bs[cur][kk][tx * 4 + 64];
            float ar8[8] = {x0.x, x0.y, x0.z, x0.w, x1.x, x1.y, x1.z, x1.w};
            float br8[8] = {y0.x, y0.y, y0.z, y0.w, y1.x, y1.y, y1.z, y1.w};
#pragma unroll
            for (int i = 0; i < 8; ++i)
#pragma unroll
                for (int j = 0; j < 8; ++j)
                    acc[i][j] += ar8[i] * br8[j];
        }
        if (nxt) {
            int nb = cur ^ 1;
            As[nb][ak + 0][ar]      = a0.x;
            As[nb][ak + 1][ar]      = a0.y;
            As[nb][ak + 2][ar]      = a0.z;
            As[nb][ak + 3][ar]      = a0.w;
            As[nb][ak + 0][ar + 64] = a1.x;
            As[nb][ak + 1][ar + 64] = a1.y;
            As[nb][ak + 2][ar + 64] = a1.z;
            As[nb][ak + 3][ar + 64] = a1.w;
        }
        CP_WAIT0();
        __syncthreads();
        cur ^= 1;
    }

    if (MODE == 0) {
        // store transposed into g_zT[b][m][o]; o contiguous
#pragma unroll
        for (int j = 0; j < 8; ++j) {
            int m = n0 + ((j < 4) ? (tx * 4 + j) : (64 + tx * 4 + (j - 4)));
            size_t base = ((size_t)b * MPTS + m) * CCH + o0 + ty * 4;
            *(float4*)&g_zT[base]      = make_float4(acc[0][j], acc[1][j], acc[2][j], acc[3][j]);
            *(float4*)&g_zT[base + 64] = make_float4(acc[4][j], acc[5][j], acc[6][j], acc[7][j]);
        }
        return;
    }

    if (MODE == 1) {
        // gather epilogue: acc[:,j] += sum_k w_k * zT[b][idx_k][o...]
#pragma unroll
        for (int j = 0; j < 8; ++j) {
            int n = n0 + ((j < 4) ? (tx * 4 + j) : (64 + tx * 4 + (j - 4)));
            size_t wb = ((size_t)b * NPTS + n) * 4;
            float4 w4 = *(const float4*)&g_w[wb];
            int4   i4 = *(const int4*)&g_idx[wb];
            float wk[3] = {w4.x, w4.y, w4.z};
            int   ik[3] = {i4.x, i4.y, i4.z};
#pragma unroll
            for (int t = 0; t < 3; ++t) {
                const float* zp = &g_zT[((size_t)b * MPTS + ik[t]) * CCH + o0 + ty * 4];
                float4 z0 = *(const float4*)zp;
                float4 z1 = *(const float4*)(zp + 64);
                acc[0][j] += wk[t] * z0.x;
                acc[1][j] += wk[t] * z0.y;
                acc[2][j] += wk[t] * z0.z;
                acc[3][j] += wk[t] * z0.w;
                acc[4][j] += wk[t] * z1.x;
                acc[5][j] += wk[t] * z1.y;
                acc[6][j] += wk[t] * z1.z;
                acc[7][j] += wk[t] * z1.w;
            }
        }
    }

#pragma unroll
    for (int i = 0; i < 8; ++i) {
        int o = o0 + ((i < 4) ? (ty * 4 + i) : (64 + ty * 4 + (i - 4)));
        float bv = bias[o];
        float4 v0, v1;
        v0.x = fmaxf(acc[i][0] + bv, 0.0f);
        v0.y = fmaxf(acc[i][1] + bv, 0.0f);
        v0.z = fmaxf(acc[i][2] + bv, 0.0f);
        v0.w = fmaxf(acc[i][3] + bv, 0.0f);
        v1.x = fmaxf(acc[i][4] + bv, 0.0f);
        v1.y = fmaxf(acc[i][5] + bv, 0.0f);
        v1.z = fmaxf(acc[i][6] + bv, 0.0f);
        v1.w = fmaxf(acc[i][7] + bv, 0.0f);
        size_t base = (size_t)o * ldn + n0 + tx * 4;
        *(float4*)&Op[base]      = v0;
        *(float4*)&Op[base + 64] = v1;
    }
}

// ---------------------------------------------------------------------------
// Fused launch: blocks [0,256) do kNN, blocks [256,512) do zGEMM (MODE 0).
// ---------------------------------------------------------------------------
__global__ void __launch_bounds__(256, 2) fused0_kernel(
    const float* __restrict__ p1, const float* __restrict__ p2,
    const float* __restrict__ W1, const float* __restrict__ f2)
{
    int bx = blockIdx.x;
    if (bx < (NPTS / 256) * BB) {
        knn_body(p1, p2, bx & 63, bx >> 6);
    } else {
        int i  = bx - (NPTS / 256) * BB;   // 0..255
        int nt = i & (MPTS / 128 - 1);     // 32 n-tiles
        int r  = i >> 5;
        int ot = r & 1;                    // 2 o-tiles
        int b  = r >> 1;                   // batch
        gemm_body<0>(W1 + CCH, 2 * CCH, f2 + (size_t)b * CCH * MPTS, MPTS, CCH,
                     nullptr, nullptr, 0, nt * 128, ot * 128, b);
    }
}

__global__ void __launch_bounds__(256, 2) gemm1_kernel(
    const float* __restrict__ W1, const float* __restrict__ f1,
    const float* __restrict__ b1)
{
    int b = blockIdx.z;
    gemm_body<1>(W1, 2 * CCH, f1 + (size_t)b * CCH * NPTS, NPTS, CCH, b1,
                 g_y1 + (size_t)b * CCH * NPTS, NPTS,
                 blockIdx.x * 128, blockIdx.y * 128, b);
}

__global__ void __launch_bounds__(256, 2) gemm2_kernel(
    const float* __restrict__ W2, const float* __restrict__ b2,
    float* __restrict__ out)
{
    int b = blockIdx.z;
    gemm_body<2>(W2, CCH, g_y1 + (size_t)b * CCH * NPTS, NPTS, CCH, b2,
                 out + (size_t)b * CCH * NPTS, NPTS,
                 blockIdx.x * 128, blockIdx.y * 128, b);
}

// ---------------------------------------------------------------------------
extern "C" void kernel_launch(void* const* d_in, const int* in_sizes, int n_in,
                              void* d_out, int out_size)
{
    const float* p1 = (const float*)d_in[0];
    const float* f1 = (const float*)d_in[1];
    const float* p2 = (const float*)d_in[2];
    const float* f2 = (const float*)d_in[3];
    const float* W1 = (const float*)d_in[4];
    const float* b1 = (const float*)d_in[5];
    const float* W2 = (const float*)d_in[6];
    const float* b2 = (const float*)d_in[7];
    float* out = (float*)d_out;

    const int GEMM_SMEM  = (2 * 16 * 132 + 2 * 16 * 128) * (int)sizeof(float); // 33280
    const int FUSED_SMEM = MPTS * 4 * (int)sizeof(float);                      // 65536

    cudaFuncSetAttribute(fused0_kernel, cudaFuncAttributeMaxDynamicSharedMemorySize, FUSED_SMEM);

    // 1) kNN (256 blocks) + zGEMM (256 blocks) fused
    fused0_kernel<<<512, 256, FUSED_SMEM>>>(p1, p2, W1, f2);

    // 2) y1 = relu(W1[:, 0:C] @ f1 + gather(zT) + b1)
    gemm1_kernel<<<dim3(NPTS / 128, CCH / 128, BB), 256, GEMM_SMEM>>>(W1, f1, b1);

    // 3) out = relu(W2 @ y1 + b2)
    gemm2_kernel<<<dim3(NPTS / 128, CCH / 128, BB), 256, GEMM_SMEM>>>(W2, b2, out);
}

// round 6
// speedup vs baseline: 1.4694x; 1.0814x over previous
#include <cuda_runtime.h>

// Problem constants
#define BB   4
#define NPTS 16384
#define MPTS 4096
#define CCH  256

// Scratch (device globals; no allocation allowed)
__device__ float g_zT[(size_t)BB * MPTS * CCH];   // [b][m][o]
__device__ float g_y1[(size_t)BB * CCH * NPTS];   // [b][o][n]
__device__ float g_w [(size_t)BB * NPTS * 4];
__device__ int   g_idx[(size_t)BB * NPTS * 4];
__device__ float g_WT1a[CCH * CCH];               // W1[:,0:C]   transposed -> [k][o]
__device__ float g_WT1b[CCH * CCH];               // W1[:,C:2C]  transposed -> [k][o]
__device__ float g_WT2 [CCH * CCH];               // W2          transposed -> [k][o]

__device__ __forceinline__ void cp_async16(void* smem_dst, const void* gmem_src) {
    unsigned s = (unsigned)__cvta_generic_to_shared(smem_dst);
    asm volatile("cp.async.cg.shared.global [%0], [%1], 16;\n" :: "r"(s), "l"(gmem_src));
}
#define CP_COMMIT() asm volatile("cp.async.commit_group;\n" ::: "memory")
#define CP_WAIT0()  asm volatile("cp.async.wait_group 0;\n" ::: "memory")

extern __shared__ float sm_f[];

// ---------------------------------------------------------------------------
// Weight transpose (runs once per launch, trivial cost).
// block = k (256 blocks), thread = o (256 threads). Writes coalesced.
// ---------------------------------------------------------------------------
__global__ void __launch_bounds__(256) transpose_w_kernel(
    const float* __restrict__ W1, const float* __restrict__ W2)
{
    int k = blockIdx.x;
    int o = threadIdx.x;
    g_WT1a[k * CCH + o] = W1[(size_t)o * (2 * CCH) + k];
    g_WT1b[k * CCH + o] = W1[(size_t)o * (2 * CCH) + CCH + k];
    g_WT2 [k * CCH + o] = W2[(size_t)o * CCH + k];
}

// ---------------------------------------------------------------------------
// kNN body: bit-exact per-op fp32 rounding (matches XLA reference).
// 4x unrolled with a min-gate: the expensive top-3 insert chain only runs
// when one of the 4 candidates beats the current 3rd-best. Insertion is done
// in ascending index order with strict '<', identical to top_k semantics.
// ---------------------------------------------------------------------------
__device__ __forceinline__ void knn_body(const float* __restrict__ p1,
                                         const float* __restrict__ p2,
                                         int tile, int b)
{
    float4* sp = (float4*)sm_f;
    const float* P2 = p2 + (size_t)b * MPTS * 3;
    for (int i = threadIdx.x; i < MPTS; i += 256) {
        float x = P2[i * 3 + 0];
        float y = P2[i * 3 + 1];
        float z = P2[i * 3 + 2];
        float s = __fadd_rn(__fadd_rn(__fmul_rn(x, x), __fmul_rn(y, y)),
                            __fmul_rn(z, z));
        sp[i] = make_float4(x, y, z, s);
    }
    __syncthreads();

    int n = tile * 256 + threadIdx.x;
    const float* q = p1 + ((size_t)b * NPTS + n) * 3;
    float px = q[0], py = q[1], pz = q[2];
    float s1 = __fadd_rn(__fadd_rn(__fmul_rn(px, px), __fmul_rn(py, py)),
                         __fmul_rn(pz, pz));

    float d0 = 3.4e38f, d1 = 3.4e38f, d2 = 3.4e38f;
    int   i0 = 0, i1 = 0, i2 = 0;
    for (int m = 0; m < MPTS; m += 4) {
        float dv[4];
#pragma unroll
        for (int u = 0; u < 4; ++u) {
            float4 c = sp[m + u];
            float dot = __fadd_rn(__fadd_rn(__fmul_rn(px, c.x),
                                            __fmul_rn(py, c.y)),
                                  __fmul_rn(pz, c.z));
            float d = __fadd_rn(s1, c.w);
            d = __fsub_rn(d, __fmul_rn(2.0f, dot));
            dv[u] = fmaxf(d, 0.0f);
        }
        float mn = fminf(fminf(dv[0], dv[1]), fminf(dv[2], dv[3]));
        if (mn < d2) {
#pragma unroll
            for (int u = 0; u < 4; ++u) {
                float d = dv[u];
                if (d < d2) {
                    if (d < d1) {
                        if (d < d0) { d2 = d1; i2 = i1; d1 = d0; i1 = i0; d0 = d; i0 = m + u; }
                        else        { d2 = d1; i2 = i1; d1 = d;  i1 = m + u; }
                    } else          { d2 = d;  i2 = m + u; }
                }
            }
        }
    }
    float r0 = __fdiv_rn(1.0f, __fadd_rn(d0, 1e-8f));
    float r1 = __fdiv_rn(1.0f, __fadd_rn(d1, 1e-8f));
    float r2 = __fdiv_rn(1.0f, __fadd_rn(d2, 1e-8f));
    float sum = __fadd_rn(__fadd_rn(r0, r1), r2);
    size_t base = ((size_t)b * NPTS + n) * 4;
    g_w[base + 0] = __fdiv_rn(r0, sum);
    g_w[base + 1] = __fdiv_rn(r1, sum);
    g_w[base + 2] = __fdiv_rn(r2, sum);
    g_w[base + 3] = 0.f;
    g_idx[base + 0] = i0; g_idx[base + 1] = i1; g_idx[base + 2] = i2; g_idx[base + 3] = 0;
}

// ---------------------------------------------------------------------------
// SGEMM 128x128 tile, kTile=32, double-buffered, cp.async for BOTH operands
// (A pre-transposed to [k][o] so no in-kernel transpose). 8x8 microtile with
// conflict-free 4+4 split. 1 barrier per 32-k step (8 total for K=256).
// Per-element accumulation order identical to previous passing kernels.
// ---------------------------------------------------------------------------
template <int MODE>
__device__ __forceinline__ void gemm_body(
    const float* __restrict__ AT,          // [K][CCH] transposed weights
    const float* __restrict__ Bp, int ldb, int K,
    const float* __restrict__ bias,
    float* __restrict__ Op, int ldn,
    int n0, int o0, int b)
{
    float (*As)[32][128] = (float(*)[32][128])sm_f;                 // 2*32*128*4 = 32768B
    float (*Bs)[32][128] = (float(*)[32][128])(sm_f + 2 * 32 * 128);

    int tid = threadIdx.x;
    int tx = tid & 15;
    int ty = tid >> 4;

    // stage-copy mapping: float4 f = tid + 256*i, i in 0..3
    int ck[4], cc[4];
#pragma unroll
    for (int i = 0; i < 4; ++i) {
        int f = tid + 256 * i;
        ck[i] = f >> 5;            // k row within stage (0..31)
        cc[i] = (f & 31) * 4;      // float col (0..124)
    }

    float acc[8][8];
#pragma unroll
    for (int i = 0; i < 8; ++i)
#pragma unroll
        for (int j = 0; j < 8; ++j) acc[i][j] = 0.0f;

    // prologue: stage 0
#pragma unroll
    for (int i = 0; i < 4; ++i) {
        cp_async16(&As[0][ck[i]][cc[i]], AT + (size_t)ck[i] * CCH + o0 + cc[i]);
        cp_async16(&Bs[0][ck[i]][cc[i]], Bp + (size_t)ck[i] * ldb + n0 + cc[i]);
    }
    CP_COMMIT();
    CP_WAIT0();
    __syncthreads();

    int cur = 0;
    for (int k0 = 0; k0 < K; k0 += 32) {
        bool nxt = (k0 + 32) < K;
        if (nxt) {
            int nb = cur ^ 1;
#pragma unroll
            for (int i = 0; i < 4; ++i) {
                cp_async16(&As[nb][ck[i]][cc[i]],
                           AT + (size_t)(k0 + 32 + ck[i]) * CCH + o0 + cc[i]);
                cp_async16(&Bs[nb][ck[i]][cc[i]],
                           Bp + (size_t)(k0 + 32 + ck[i]) * ldb + n0 + cc[i]);
            }
            CP_COMMIT();
        }
#pragma unroll
        for (int kk = 0; kk < 32; ++kk) {
            float4 x0 = *(const float4*)&As[cur][kk][ty * 4];
            float4 x1 = *(const float4*)&As[cur][kk][ty * 4 + 64];
            float4 y0 = *(const float4*)&Bs[cur][kk][tx * 4];
            float4 y1 = *(const float4*)&Bs[cur][kk][tx * 4 + 64];
            float ar8[8] = {x0.x, x0.y, x0.z, x0.w, x1.x, x1.y, x1.z, x1.w};
            float br8[8] = {y0.x, y0.y, y0.z, y0.w, y1.x, y1.y, y1.z, y1.w};
#pragma unroll
            for (int i = 0; i < 8; ++i)
#pragma unroll
                for (int j = 0; j < 8; ++j)
                    acc[i][j] += ar8[i] * br8[j];
        }
        CP_WAIT0();
        __syncthreads();
        cur ^= 1;
    }

    if (MODE == 0) {
        // store transposed into g_zT[b][m][o]; o contiguous
#pragma unroll
        for (int j = 0; j < 8; ++j) {
            int m = n0 + ((j < 4) ? (tx * 4 + j) : (64 + tx * 4 + (j - 4)));
            size_t base = ((size_t)b * MPTS + m) * CCH + o0 + ty * 4;
            *(float4*)&g_zT[base]      = make_float4(acc[0][j], acc[1][j], acc[2][j], acc[3][j]);
            *(float4*)&g_zT[base + 64] = make_float4(acc[4][j], acc[5][j], acc[6][j], acc[7][j]);
        }
        return;
    }

    if (MODE == 1) {
        // gather epilogue: acc[:,j] += sum_k w_k * zT[b][idx_k][o...]
#pragma unroll
        for (int j = 0; j < 8; ++j) {
            int n = n0 + ((j < 4) ? (tx * 4 + j) : (64 + tx * 4 + (j - 4)));
            size_t wb = ((size_t)b * NPTS + n) * 4;
            float4 w4 = *(const float4*)&g_w[wb];
            int4   i4 = *(const int4*)&g_idx[wb];
            float wk[3] = {w4.x, w4.y, w4.z};
            int   ik[3] = {i4.x, i4.y, i4.z};
#pragma unroll
            for (int t = 0; t < 3; ++t) {
                const float* zp = &g_zT[((size_t)b * MPTS + ik[t]) * CCH + o0 + ty * 4];
                float4 z0 = *(const float4*)zp;
                float4 z1 = *(const float4*)(zp + 64);
                acc[0][j] += wk[t] * z0.x;
                acc[1][j] += wk[t] * z0.y;
                acc[2][j] += wk[t] * z0.z;
                acc[3][j] += wk[t] * z0.w;
                acc[4][j] += wk[t] * z1.x;
                acc[5][j] += wk[t] * z1.y;
                acc[6][j] += wk[t] * z1.z;
                acc[7][j] += wk[t] * z1.w;
            }
        }
    }

#pragma unroll
    for (int i = 0; i < 8; ++i) {
        int o = o0 + ((i < 4) ? (ty * 4 + i) : (64 + ty * 4 + (i - 4)));
        float bv = bias[o];
        float4 v0, v1;
        v0.x = fmaxf(acc[i][0] + bv, 0.0f);
        v0.y = fmaxf(acc[i][1] + bv, 0.0f);
        v0.z = fmaxf(acc[i][2] + bv, 0.0f);
        v0.w = fmaxf(acc[i][3] + bv, 0.0f);
        v1.x = fmaxf(acc[i][4] + bv, 0.0f);
        v1.y = fmaxf(acc[i][5] + bv, 0.0f);
        v1.z = fmaxf(acc[i][6] + bv, 0.0f);
        v1.w = fmaxf(acc[i][7] + bv, 0.0f);
        size_t base = (size_t)o * ldn + n0 + tx * 4;
        *(float4*)&Op[base]      = v0;
        *(float4*)&Op[base + 64] = v1;
    }
}

// ---------------------------------------------------------------------------
// Fused launch: blocks [0,256) do kNN, blocks [256,512) do zGEMM (MODE 0).
// ---------------------------------------------------------------------------
__global__ void __launch_bounds__(256, 2) fused0_kernel(
    const float* __restrict__ p1, const float* __restrict__ p2,
    const float* __restrict__ f2)
{
    int bx = blockIdx.x;
    if (bx < (NPTS / 256) * BB) {
        knn_body(p1, p2, bx & 63, bx >> 6);
    } else {
        int i  = bx - (NPTS / 256) * BB;   // 0..255
        int nt = i & (MPTS / 128 - 1);     // 32 n-tiles
        int r  = i >> 5;
        int ot = r & 1;                    // 2 o-tiles
        int b  = r >> 1;                   // batch
        gemm_body<0>(g_WT1b, f2 + (size_t)b * CCH * MPTS, MPTS, CCH,
                     nullptr, nullptr, 0, nt * 128, ot * 128, b);
    }
}

__global__ void __launch_bounds__(256, 2) gemm1_kernel(
    const float* __restrict__ f1, const float* __restrict__ b1)
{
    int b = blockIdx.z;
    gemm_body<1>(g_WT1a, f1 + (size_t)b * CCH * NPTS, NPTS, CCH, b1,
                 g_y1 + (size_t)b * CCH * NPTS, NPTS,
                 blockIdx.x * 128, blockIdx.y * 128, b);
}

__global__ void __launch_bounds__(256, 2) gemm2_kernel(
    const float* __restrict__ b2, float* __restrict__ out)
{
    int b = blockIdx.z;
    gemm_body<2>(g_WT2, g_y1 + (size_t)b * CCH * NPTS, NPTS, CCH, b2,
                 out + (size_t)b * CCH * NPTS, NPTS,
                 blockIdx.x * 128, blockIdx.y * 128, b);
}

// ---------------------------------------------------------------------------
extern "C" void kernel_launch(void* const* d_in, const int* in_sizes, int n_in,
                              void* d_out, int out_size)
{
    const float* p1 = (const float*)d_in[0];
    const float* f1 = (const float*)d_in[1];
    const float* p2 = (const float*)d_in[2];
    const float* f2 = (const float*)d_in[3];
    const float* W1 = (const float*)d_in[4];
    const float* b1 = (const float*)d_in[5];
    const float* W2 = (const float*)d_in[6];
    const float* b2 = (const float*)d_in[7];
    float* out = (float*)d_out;

    const int GEMM_SMEM  = 2 * (2 * 32 * 128) * (int)sizeof(float); // 65536
    const int FUSED_SMEM = MPTS * 4 * (int)sizeof(float);           // 65536

    cudaFuncSetAttribute(fused0_kernel, cudaFuncAttributeMaxDynamicSharedMemorySize, FUSED_SMEM);
    cudaFuncSetAttribute(gemm1_kernel,  cudaFuncAttributeMaxDynamicSharedMemorySize, GEMM_SMEM);
    cudaFuncSetAttribute(gemm2_kernel,  cudaFuncAttributeMaxDynamicSharedMemorySize, GEMM_SMEM);

    // 0) transpose weights into [k][o] layout
    transpose_w_kernel<<<CCH, CCH>>>(W1, W2);

    // 1) kNN (256 blocks) + zGEMM (256 blocks) fused
    fused0_kernel<<<512, 256, FUSED_SMEM>>>(p1, p2, f2);

    // 2) y1 = relu(W1[:, 0:C] @ f1 + gather(zT) + b1)
    gemm1_kernel<<<dim3(NPTS / 128, CCH / 128, BB), 256, GEMM_SMEM>>>(f1, b1);

    // 3) out = relu(W2 @ y1 + b2)
    gemm2_kernel<<<dim3(NPTS / 128, CCH / 128, BB), 256, GEMM_SMEM>>>(b2, out);
}

// round 8
// speedup vs baseline: 1.6949x; 1.1535x over previous
#include <cuda_runtime.h>

// Problem constants
#define BB   4
#define NPTS 16384
#define MPTS 4096
#define CCH  256

typedef unsigned long long ull;

// Scratch (device globals; no allocation allowed)
__device__ float g_zT[(size_t)BB * MPTS * CCH];   // [b][m][o]
__device__ float g_y1[(size_t)BB * CCH * NPTS];   // [b][o][n]
__device__ float g_w [(size_t)BB * NPTS * 4];
__device__ int   g_idx[(size_t)BB * NPTS * 4];
__device__ float g_WT1a[CCH * CCH];               // W1[:,0:C]   transposed -> [k][o]
__device__ float g_WT1b[CCH * CCH];               // W1[:,C:2C]  transposed -> [k][o]
__device__ float g_WT2 [CCH * CCH];               // W2          transposed -> [k][o]

__device__ __forceinline__ void cp_async16(void* smem_dst, const void* gmem_src) {
    unsigned s = (unsigned)__cvta_generic_to_shared(smem_dst);
    asm volatile("cp.async.cg.shared.global [%0], [%1], 16;\n" :: "r"(s), "l"(gmem_src));
}
#define CP_COMMIT() asm volatile("cp.async.commit_group;\n" ::: "memory")
#define CP_WAIT0()  asm volatile("cp.async.wait_group 0;\n" ::: "memory")

// ---- packed f32x2 FMA (single fused op per lane; per-lane rn rounding is
//      identical to the scalar FFMA chain -> bit-exact vs verified kernel) ----
__device__ __forceinline__ void ffma2(ull& c, ull a, ull b) {
    asm("fma.rn.f32x2 %0, %1, %2, %0;" : "+l"(c) : "l"(a), "l"(b));
}
__device__ __forceinline__ ull pack2(float lo, float hi) {
    ull r;
    asm("mov.b64 %0, {%1, %2};" : "=l"(r) : "f"(lo), "f"(hi));
    return r;
}
__device__ __forceinline__ float2 unpack2(ull v) {
    float lo, hi;
    asm("mov.b64 {%0, %1}, %2;" : "=f"(lo), "=f"(hi) : "l"(v));
    return make_float2(lo, hi);
}

extern __shared__ float sm_f[];

// ---------------------------------------------------------------------------
// Weight transpose (runs once per launch, trivial cost).
// ---------------------------------------------------------------------------
__global__ void __launch_bounds__(256) transpose_w_kernel(
    const float* __restrict__ W1, const float* __restrict__ W2)
{
    int k = blockIdx.x;
    int o = threadIdx.x;
    g_WT1a[k * CCH + o] = W1[(size_t)o * (2 * CCH) + k];
    g_WT1b[k * CCH + o] = W1[(size_t)o * (2 * CCH) + CCH + k];
    g_WT2 [k * CCH + o] = W2[(size_t)o * CCH + k];
}

// ---------------------------------------------------------------------------
// kNN body: VERIFIED bit-exact scalar version (rel_err 7.2e-6 in R6).
// Per-op fp32 rounding via __f*_rn intrinsics (contraction-proof by spec).
// 4x unrolled with min-gate; insert chain in ascending index order with
// strict '<' — identical to jax top_k semantics. DO NOT pack this math:
// packed mul/add f32x2 gets FMA-contracted and flips near-tie neighbors.
// ---------------------------------------------------------------------------
__device__ __forceinline__ void knn_body(const float* __restrict__ p1,
                                         const float* __restrict__ p2,
                                         int tile, int b)
{
    float* sx = sm_f;
    float* sy = sm_f + MPTS;
    float* sz = sm_f + 2 * MPTS;
    float* ss = sm_f + 3 * MPTS;
    const float* P2 = p2 + (size_t)b * MPTS * 3;
    for (int i = threadIdx.x; i < MPTS; i += 256) {
        float x = P2[i * 3 + 0];
        float y = P2[i * 3 + 1];
        float z = P2[i * 3 + 2];
        sx[i] = x; sy[i] = y; sz[i] = z;
        ss[i] = __fadd_rn(__fadd_rn(__fmul_rn(x, x), __fmul_rn(y, y)),
                          __fmul_rn(z, z));
    }
    __syncthreads();

    int n = tile * 256 + threadIdx.x;
    const float* q = p1 + ((size_t)b * NPTS + n) * 3;
    float px = q[0], py = q[1], pz = q[2];
    float s1 = __fadd_rn(__fadd_rn(__fmul_rn(px, px), __fmul_rn(py, py)),
                         __fmul_rn(pz, pz));

    float d0 = 3.4e38f, d1 = 3.4e38f, d2 = 3.4e38f;
    int   i0 = 0, i1 = 0, i2 = 0;
    for (int m = 0; m < MPTS; m += 4) {
        float dv[4];
#pragma unroll
        for (int u = 0; u < 4; ++u) {
            float dot = __fadd_rn(__fadd_rn(__fmul_rn(px, sx[m + u]),
                                            __fmul_rn(py, sy[m + u])),
                                  __fmul_rn(pz, sz[m + u]));
            float d = __fadd_rn(s1, ss[m + u]);
            d = __fsub_rn(d, __fmul_rn(2.0f, dot));
            dv[u] = fmaxf(d, 0.0f);
        }
        float mn = fminf(fminf(dv[0], dv[1]), fminf(dv[2], dv[3]));
        if (mn < d2) {
#pragma unroll
            for (int u = 0; u < 4; ++u) {
                float d = dv[u];
                if (d < d2) {
                    if (d < d1) {
                        if (d < d0) { d2 = d1; i2 = i1; d1 = d0; i1 = i0; d0 = d; i0 = m + u; }
                        else        { d2 = d1; i2 = i1; d1 = d;  i1 = m + u; }
                    } else          { d2 = d;  i2 = m + u; }
                }
            }
        }
    }
    float r0 = __fdiv_rn(1.0f, __fadd_rn(d0, 1e-8f));
    float r1 = __fdiv_rn(1.0f, __fadd_rn(d1, 1e-8f));
    float r2 = __fdiv_rn(1.0f, __fadd_rn(d2, 1e-8f));
    float sum = __fadd_rn(__fadd_rn(r0, r1), r2);
    size_t base = ((size_t)b * NPTS + n) * 4;
    g_w[base + 0] = __fdiv_rn(r0, sum);
    g_w[base + 1] = __fdiv_rn(r1, sum);
    g_w[base + 2] = __fdiv_rn(r2, sum);
    g_w[base + 3] = 0.f;
    g_idx[base + 0] = i0; g_idx[base + 1] = i1; g_idx[base + 2] = i2; g_idx[base + 3] = 0;
}

// ---------------------------------------------------------------------------
// SGEMM 128x128, kTile=32, double-buffered cp.async both operands.
// Inner loop uses fma.rn.f32x2: acc pairs along the o-dim (adjacent in As ->
// 64-bit shared loads, no pack), b values lane-duplicated (8 packs / kk).
// Per-element accumulation order identical to verified scalar kernel.
// ---------------------------------------------------------------------------
template <int MODE>
__device__ __forceinline__ void gemm_body(
    const float* __restrict__ AT,          // [K][CCH] transposed weights
    const float* __restrict__ Bp, int ldb, int K,
    const float* __restrict__ bias,
    float* __restrict__ Op, int ldn,
    int n0, int o0, int b)
{
    float (*As)[32][128] = (float(*)[32][128])sm_f;                 // 32KB
    float (*Bs)[32][128] = (float(*)[32][128])(sm_f + 2 * 32 * 128);

    int tid = threadIdx.x;
    int tx = tid & 15;
    int ty = tid >> 4;

    int ck[4], cc[4];
#pragma unroll
    for (int i = 0; i < 4; ++i) {
        int f = tid + 256 * i;
        ck[i] = f >> 5;
        cc[i] = (f & 31) * 4;
    }

    ull acc2[4][8];
#pragma unroll
    for (int i = 0; i < 4; ++i)
#pragma unroll
        for (int j = 0; j < 8; ++j) acc2[i][j] = 0ull;

    // prologue: stage 0
#pragma unroll
    for (int i = 0; i < 4; ++i) {
        cp_async16(&As[0][ck[i]][cc[i]], AT + (size_t)ck[i] * CCH + o0 + cc[i]);
        cp_async16(&Bs[0][ck[i]][cc[i]], Bp + (size_t)ck[i] * ldb + n0 + cc[i]);
    }
    CP_COMMIT();
    CP_WAIT0();
    __syncthreads();

    int cur = 0;
    for (int k0 = 0; k0 < K; k0 += 32) {
        bool nxt = (k0 + 32) < K;
        if (nxt) {
            int nb = cur ^ 1;
#pragma unroll
            for (int i = 0; i < 4; ++i) {
                cp_async16(&As[nb][ck[i]][cc[i]],
                           AT + (size_t)(k0 + 32 + ck[i]) * CCH + o0 + cc[i]);
                cp_async16(&Bs[nb][ck[i]][cc[i]],
                           Bp + (size_t)(k0 + 32 + ck[i]) * ldb + n0 + cc[i]);
            }
            CP_COMMIT();
        }
#pragma unroll
        for (int kk = 0; kk < 32; ++kk) {
            ull aa[4];
            aa[0] = *(const ull*)&As[cur][kk][ty * 4];          // o pair (0,1)
            aa[1] = *(const ull*)&As[cur][kk][ty * 4 + 2];      // o pair (2,3)
            aa[2] = *(const ull*)&As[cur][kk][ty * 4 + 64];     // o pair (4,5)
            aa[3] = *(const ull*)&As[cur][kk][ty * 4 + 66];     // o pair (6,7)
            float4 y0 = *(const float4*)&Bs[cur][kk][tx * 4];
            float4 y1 = *(const float4*)&Bs[cur][kk][tx * 4 + 64];
            ull bb[8];
            bb[0] = pack2(y0.x, y0.x);
            bb[1] = pack2(y0.y, y0.y);
            bb[2] = pack2(y0.z, y0.z);
            bb[3] = pack2(y0.w, y0.w);
            bb[4] = pack2(y1.x, y1.x);
            bb[5] = pack2(y1.y, y1.y);
            bb[6] = pack2(y1.z, y1.z);
            bb[7] = pack2(y1.w, y1.w);
#pragma unroll
            for (int ip = 0; ip < 4; ++ip)
#pragma unroll
                for (int j = 0; j < 8; ++j)
                    ffma2(acc2[ip][j], aa[ip], bb[j]);
        }
        CP_WAIT0();
        __syncthreads();
        cur ^= 1;
    }

    // unpack to scalar acc[i][j] (i = o index within microtile, j = n index)
    float acc[8][8];
#pragma unroll
    for (int ip = 0; ip < 4; ++ip)
#pragma unroll
        for (int j = 0; j < 8; ++j) {
            float2 f = unpack2(acc2[ip][j]);
            acc[2 * ip + 0][j] = f.x;
            acc[2 * ip + 1][j] = f.y;
        }

    if (MODE == 0) {
#pragma unroll
        for (int j = 0; j < 8; ++j) {
            int m = n0 + ((j < 4) ? (tx * 4 + j) : (64 + tx * 4 + (j - 4)));
            size_t base = ((size_t)b * MPTS + m) * CCH + o0 + ty * 4;
            *(float4*)&g_zT[base]      = make_float4(acc[0][j], acc[1][j], acc[2][j], acc[3][j]);
            *(float4*)&g_zT[base + 64] = make_float4(acc[4][j], acc[5][j], acc[6][j], acc[7][j]);
        }
        return;
    }

    if (MODE == 1) {
#pragma unroll
        for (int j = 0; j < 8; ++j) {
            int n = n0 + ((j < 4) ? (tx * 4 + j) : (64 + tx * 4 + (j - 4)));
            size_t wb = ((size_t)b * NPTS + n) * 4;
            float4 w4 = *(const float4*)&g_w[wb];
            int4   i4 = *(const int4*)&g_idx[wb];
            float wk[3] = {w4.x, w4.y, w4.z};
            int   ik[3] = {i4.x, i4.y, i4.z};
#pragma unroll
            for (int t = 0; t < 3; ++t) {
                const float* zp = &g_zT[((size_t)b * MPTS + ik[t]) * CCH + o0 + ty * 4];
                float4 z0 = *(const float4*)zp;
                float4 z1 = *(const float4*)(zp + 64);
                acc[0][j] += wk[t] * z0.x;
                acc[1][j] += wk[t] * z0.y;
                acc[2][j] += wk[t] * z0.z;
                acc[3][j] += wk[t] * z0.w;
                acc[4][j] += wk[t] * z1.x;
                acc[5][j] += wk[t] * z1.y;
                acc[6][j] += wk[t] * z1.z;
                acc[7][j] += wk[t] * z1.w;
            }
        }
    }

#pragma unroll
    for (int i = 0; i < 8; ++i) {
        int o = o0 + ((i < 4) ? (ty * 4 + i) : (64 + ty * 4 + (i - 4)));
        float bv = bias[o];
        float4 v0, v1;
        v0.x = fmaxf(acc[i][0] + bv, 0.0f);
        v0.y = fmaxf(acc[i][1] + bv, 0.0f);
        v0.z = fmaxf(acc[i][2] + bv, 0.0f);
        v0.w = fmaxf(acc[i][3] + bv, 0.0f);
        v1.x = fmaxf(acc[i][4] + bv, 0.0f);
        v1.y = fmaxf(acc[i][5] + bv, 0.0f);
        v1.z = fmaxf(acc[i][6] + bv, 0.0f);
        v1.w = fmaxf(acc[i][7] + bv, 0.0f);
        size_t base = (size_t)o * ldn + n0 + tx * 4;
        *(float4*)&Op[base]      = v0;
        *(float4*)&Op[base + 64] = v1;
    }
}

// ---------------------------------------------------------------------------
// Fused launch: blocks [0,256) do kNN, blocks [256,512) do zGEMM (MODE 0).
// ---------------------------------------------------------------------------
__global__ void __launch_bounds__(256, 2) fused0_kernel(
    const float* __restrict__ p1, const float* __restrict__ p2,
    const float* __restrict__ f2)
{
    int bx = blockIdx.x;
    if (bx < (NPTS / 256) * BB) {
        knn_body(p1, p2, bx & 63, bx >> 6);
    } else {
        int i  = bx - (NPTS / 256) * BB;
        int nt = i & (MPTS / 128 - 1);
        int r  = i >> 5;
        int ot = r & 1;
        int b  = r >> 1;
        gemm_body<0>(g_WT1b, f2 + (size_t)b * CCH * MPTS, MPTS, CCH,
                     nullptr, nullptr, 0, nt * 128, ot * 128, b);
    }
}

__global__ void __launch_bounds__(256, 2) gemm1_kernel(
    const float* __restrict__ f1, const float* __restrict__ b1)
{
    int b = blockIdx.z;
    gemm_body<1>(g_WT1a, f1 + (size_t)b * CCH * NPTS, NPTS, CCH, b1,
                 g_y1 + (size_t)b * CCH * NPTS, NPTS,
                 blockIdx.x * 128, blockIdx.y * 128, b);
}

__global__ void __launch_bounds__(256, 2) gemm2_kernel(
    const float* __restrict__ b2, float* __restrict__ out)
{
    int b = blockIdx.z;
    gemm_body<2>(g_WT2, g_y1 + (size_t)b * CCH * NPTS, NPTS, CCH, b2,
                 out + (size_t)b * CCH * NPTS, NPTS,
                 blockIdx.x * 128, blockIdx.y * 128, b);
}

// ---------------------------------------------------------------------------
extern "C" void kernel_launch(void* const* d_in, const int* in_sizes, int n_in,
                              void* d_out, int out_size)
{
    const float* p1 = (const float*)d_in[0];
    const float* f1 = (const float*)d_in[1];
    const float* p2 = (const float*)d_in[2];
    const float* f2 = (const float*)d_in[3];
    const float* W1 = (const float*)d_in[4];
    const float* b1 = (const float*)d_in[5];
    const float* W2 = (const float*)d_in[6];
    const float* b2 = (const float*)d_in[7];
    float* out = (float*)d_out;

    const int GEMM_SMEM  = 2 * (2 * 32 * 128) * (int)sizeof(float); // 65536
    const int FUSED_SMEM = MPTS * 4 * (int)sizeof(float);           // 65536

    cudaFuncSetAttribute(fused0_kernel, cudaFuncAttributeMaxDynamicSharedMemorySize, FUSED_SMEM);
    cudaFuncSetAttribute(gemm1_kernel,  cudaFuncAttributeMaxDynamicSharedMemorySize, GEMM_SMEM);
    cudaFuncSetAttribute(gemm2_kernel,  cudaFuncAttributeMaxDynamicSharedMemorySize, GEMM_SMEM);

    // 0) transpose weights into [k][o] layout
    transpose_w_kernel<<<CCH, CCH>>>(W1, W2);

    // 1) kNN (256 blocks) + zGEMM (256 blocks) fused
    fused0_kernel<<<512, 256, FUSED_SMEM>>>(p1, p2, f2);

    // 2) y1 = relu(W1[:, 0:C] @ f1 + gather(zT) + b1)
    gemm1_kernel<<<dim3(NPTS / 128, CCH / 128, BB), 256, GEMM_SMEM>>>(f1, b1);

    // 3) out = relu(W2 @ y1 + b2)
    gemm2_kernel<<<dim3(NPTS / 128, CCH / 128, BB), 256, GEMM_SMEM>>>(b2, out);
}